// round 6
// baseline (speedup 1.0000x reference)
#include <cuda_runtime.h>
#include <math.h>

#define B 32
#define N 2048
#define H 256
#define F 8
#define NH 8
#define DH 32
#define C 64
#define STEPS 3
#define NSPLIT 4
#define TN 128
#define NCHUNK 16   // k2 grid.x = score chunks

typedef unsigned long long ull;

__device__ float  g_U[B * H * C];
__device__ float  g_const[B * C];
__device__ float  g_scores[(size_t)B * N * C];
__device__ float2 g_part[B * NCHUNK * C];
__device__ float  g_Wpart[B * NSPLIT * H * C];
__device__ float  g_ho[F * B * H];

__device__ __forceinline__ ull pack2(float x, float y) {
    ull r; asm("mov.b64 %0, {%1, %2};" : "=l"(r) : "f"(x), "f"(y)); return r;
}
__device__ __forceinline__ float2 unpack2(ull v) {
    float2 r; asm("mov.b64 {%0, %1}, %2;" : "=f"(r.x), "=f"(r.y) : "l"(v)); return r;
}
__device__ __forceinline__ void fma2(ull& a, ull x, ull y) {
    asm("fma.rn.f32x2 %0, %1, %2, %0;" : "+l"(a) : "l"(x), "l"(y));
}

// ============ K1: qh = Wq q + bq ; U = Wk^T qh / sqrt(dh) ; const = qh.bk/sqrt(dh)
__global__ void __launch_bounds__(256) k1_prep(const float* __restrict__ q,
                                               const float* __restrict__ Wi,
                                               const float* __restrict__ bi) {
    int f = blockIdx.x & (F - 1);
    int b = blockIdx.x >> 3;
    __shared__ float qs[H];
    __shared__ float qhs[H];
    int t = threadIdx.x, lane = t & 31, w = t >> 5;
    qs[t] = q[b * H + t];
    __syncthreads();

    const float* Wq = Wi + (size_t)f * 3 * H * H;
    const float* bq = bi + f * 3 * H;
    for (int i0 = w * 32; i0 < w * 32 + 32; i0 += 4) {
        float s0 = 0.f, s1 = 0.f, s2 = 0.f, s3 = 0.f;
        for (int j = lane; j < H; j += 32) {
            float qv = qs[j];
            s0 = fmaf(Wq[(size_t)(i0 + 0) * H + j], qv, s0);
            s1 = fmaf(Wq[(size_t)(i0 + 1) * H + j], qv, s1);
            s2 = fmaf(Wq[(size_t)(i0 + 2) * H + j], qv, s2);
            s3 = fmaf(Wq[(size_t)(i0 + 3) * H + j], qv, s3);
        }
        #pragma unroll
        for (int o = 16; o; o >>= 1) {
            s0 += __shfl_xor_sync(0xffffffffu, s0, o);
            s1 += __shfl_xor_sync(0xffffffffu, s1, o);
            s2 += __shfl_xor_sync(0xffffffffu, s2, o);
            s3 += __shfl_xor_sync(0xffffffffu, s3, o);
        }
        if (lane == 0) {
            qhs[i0 + 0] = s0 + bq[i0 + 0];
            qhs[i0 + 1] = s1 + bq[i0 + 1];
            qhs[i0 + 2] = s2 + bq[i0 + 2];
            qhs[i0 + 3] = s3 + bq[i0 + 3];
        }
    }
    __syncthreads();

    const float invs = 0.17677669529663687f;
    const float* Wk = Wi + (size_t)f * 3 * H * H + (size_t)H * H;
    float uo[NH];
    #pragma unroll
    for (int h = 0; h < NH; ++h) {
        float s = 0.f;
        #pragma unroll 8
        for (int j = 0; j < DH; ++j)
            s = fmaf(qhs[h * DH + j], Wk[(size_t)(h * DH + j) * H + t], s);
        uo[h] = s * invs;
    }
    float* up = g_U + ((size_t)(b * H + t)) * C + f * NH;
    *(float4*)up       = make_float4(uo[0], uo[1], uo[2], uo[3]);
    *(float4*)(up + 4) = make_float4(uo[4], uo[5], uo[6], uo[7]);

    if (t < NH) {
        const float* bk = bi + f * 3 * H + H;
        float s = 0.f;
        for (int j = 0; j < DH; ++j) s += qhs[t * DH + j] * bk[t * DH + j];
        g_const[b * C + t * 1 + 0 + f * NH] = s * invs;
    }
}

// ============ K2: scores GEMM (double-buffered) + fused partial softmax stats
__global__ void __launch_bounds__(256) k2_scores(const float* __restrict__ docs,
                                                 const float* __restrict__ cw) {
    int b = blockIdx.y;
    int chunk = blockIdx.x;
    int n0 = chunk * TN;
    __shared__ __align__(16) float Ds[32 * 132];
    __shared__ __align__(16) float Us[32 * 64];
    int t = threadIdx.x;
    int rowg = (t >> 3) << 2;
    int colg = (t & 7) << 3;
    ull acc[4][4];
    #pragma unroll
    for (int r = 0; r < 4; ++r)
        #pragma unroll
        for (int p = 0; p < 4; ++p) acc[r][p] = 0ull;

    const float* Db = docs + ((size_t)b * N + n0) * H;
    const float* Ub = g_U + (size_t)b * H * C;
    int lk = (t & 7) << 2;
    int lr = t >> 3;
    int uk = t >> 3;
    int uc = (t & 7) << 3;

    float4 pd[4], pu0, pu1;
    #pragma unroll
    for (int it = 0; it < 4; ++it)
        pd[it] = *(const float4*)(Db + (size_t)(lr + (it << 5)) * H + lk);
    pu0 = *(const float4*)(Ub + (size_t)uk * C + uc);
    pu1 = *(const float4*)(Ub + (size_t)uk * C + uc + 4);

    for (int k0 = 0; k0 < H; k0 += 32) {
        if (k0) __syncthreads();
        #pragma unroll
        for (int it = 0; it < 4; ++it) {
            int r = lr + (it << 5);
            Ds[(lk + 0) * 132 + r] = pd[it].x;
            Ds[(lk + 1) * 132 + r] = pd[it].y;
            Ds[(lk + 2) * 132 + r] = pd[it].z;
            Ds[(lk + 3) * 132 + r] = pd[it].w;
        }
        *(float4*)&Us[uk * 64 + uc]     = pu0;
        *(float4*)&Us[uk * 64 + uc + 4] = pu1;
        if (k0 + 32 < H) {
            #pragma unroll
            for (int it = 0; it < 4; ++it)
                pd[it] = *(const float4*)(Db + (size_t)(lr + (it << 5)) * H + (k0 + 32 + lk));
            pu0 = *(const float4*)(Ub + (size_t)(k0 + 32 + uk) * C + uc);
            pu1 = *(const float4*)(Ub + (size_t)(k0 + 32 + uk) * C + uc + 4);
        }
        __syncthreads();

        #pragma unroll 8
        for (int k = 0; k < 32; ++k) {
            float4 d4 = *(const float4*)&Ds[k * 132 + rowg];
            ull u0 = *(const ull*)&Us[k * 64 + colg];
            ull u1 = *(const ull*)&Us[k * 64 + colg + 2];
            ull u2 = *(const ull*)&Us[k * 64 + colg + 4];
            ull u3 = *(const ull*)&Us[k * 64 + colg + 6];
            ull dd;
            dd = pack2(d4.x, d4.x);
            fma2(acc[0][0], dd, u0); fma2(acc[0][1], dd, u1); fma2(acc[0][2], dd, u2); fma2(acc[0][3], dd, u3);
            dd = pack2(d4.y, d4.y);
            fma2(acc[1][0], dd, u0); fma2(acc[1][1], dd, u1); fma2(acc[1][2], dd, u2); fma2(acc[1][3], dd, u3);
            dd = pack2(d4.z, d4.z);
            fma2(acc[2][0], dd, u0); fma2(acc[2][1], dd, u1); fma2(acc[2][2], dd, u2); fma2(acc[2][3], dd, u3);
            dd = pack2(d4.w, d4.w);
            fma2(acc[3][0], dd, u0); fma2(acc[3][1], dd, u1); fma2(acc[3][2], dd, u2); fma2(acc[3][3], dd, u3);
        }
    }

    // epilogue: o = cw * acc + const ; write scores
    float cst[8];
    #pragma unroll
    for (int c = 0; c < 8; ++c) cst[c] = g_const[b * C + colg + c];
    const float* cwp = cw + (size_t)b * N + n0;
    float o[4][8];
    #pragma unroll
    for (int r = 0; r < 4; ++r) {
        float cwv = cwp[rowg + r];
        #pragma unroll
        for (int p = 0; p < 4; ++p) {
            float2 v = unpack2(acc[r][p]);
            o[r][2 * p]     = fmaf(cwv, v.x, cst[2 * p]);
            o[r][2 * p + 1] = fmaf(cwv, v.y, cst[2 * p + 1]);
        }
        float* sp = g_scores + ((size_t)b * N + n0 + rowg + r) * C + colg;
        *(float4*)sp       = make_float4(o[r][0], o[r][1], o[r][2], o[r][3]);
        *(float4*)(sp + 4) = make_float4(o[r][4], o[r][5], o[r][6], o[r][7]);
    }

    // fused partial softmax stats over this chunk's 128 rows
    __syncthreads();                  // done with Ds/Us for GEMM
    float* red  = Ds;                 // reuse: [32][65]
    float* smax = Us;                 // reuse: [64]
    int j = t >> 3;
    #pragma unroll
    for (int c = 0; c < 8; ++c) {
        float lm = fmaxf(fmaxf(o[0][c], o[1][c]), fmaxf(o[2][c], o[3][c]));
        red[j * 65 + colg + c] = lm;
    }
    __syncthreads();
    if (t < 64) {
        float m = -1e30f;
        #pragma unroll
        for (int jj = 0; jj < 32; ++jj) m = fmaxf(m, red[jj * 65 + t]);
        smax[t] = m;
    }
    __syncthreads();
    #pragma unroll
    for (int c = 0; c < 8; ++c) {
        float m = smax[colg + c];
        float ls = __expf(o[0][c] - m) + __expf(o[1][c] - m) +
                   __expf(o[2][c] - m) + __expf(o[3][c] - m);
        red[j * 65 + colg + c] = ls;
    }
    __syncthreads();
    if (t < 64) {
        float l = 0.f;
        #pragma unroll
        for (int jj = 0; jj < 32; ++jj) l += red[jj * 65 + t];
        g_part[(b * NCHUNK + chunk) * C + t] = make_float2(smax[t], l);
    }
}

// ============ K4: fused stat-merge + Wpart GEMM (double-buffered)
__global__ void __launch_bounds__(256) k4_wgemm(const float* __restrict__ docs,
                                                const float* __restrict__ cw) {
    int b = blockIdx.y, ns = blockIdx.x;
    int n0 = ns * (N / NSPLIT);
    __shared__ __align__(16) float Dn[32 * 260];
    __shared__ __align__(16) float As[32 * 64];
    __shared__ float msh[64], ilh[64];
    int t = threadIdx.x;

    if (t < 64) {
        float2 pc[NCHUNK];
        float m = -1e30f;
        #pragma unroll
        for (int ch = 0; ch < NCHUNK; ++ch) {
            pc[ch] = g_part[(b * NCHUNK + ch) * C + t];
            m = fmaxf(m, pc[ch].x);
        }
        float l = 0.f;
        #pragma unroll
        for (int ch = 0; ch < NCHUNK; ++ch) l += pc[ch].y * __expf(pc[ch].x - m);
        msh[t] = m; ilh[t] = 1.0f / l;
    }
    __syncthreads();
    float mC = msh[t & 63], iC = ilh[t & 63];

    int rowg = (t >> 3) << 3;
    int colg = (t & 7) << 3;
    ull acc[8][4];
    #pragma unroll
    for (int r = 0; r < 8; ++r)
        #pragma unroll
        for (int p = 0; p < 4; ++p) acc[r][p] = 0ull;

    float4 pd[8];
    float  ps[8], pcw[8];
    int kq = (t & 63) << 2;
    int nnb = t >> 6;

    // prefetch nc = 0
    {
        const float* Dg = docs + ((size_t)b * N + n0) * H;
        const float* Sg = g_scores + ((size_t)b * N + n0) * C;
        const float* Cg = cw + (size_t)b * N + n0;
        #pragma unroll
        for (int i = 0; i < 8; ++i) {
            int nn = nnb + (i << 2);
            pd[i] = *(const float4*)(Dg + (size_t)nn * H + kq);
            ps[i] = Sg[(size_t)nn * C + (t & 63)];
            pcw[i] = Cg[nn];
        }
    }

    for (int nc = 0; nc < N / NSPLIT; nc += 32) {
        if (nc) __syncthreads();
        #pragma unroll
        for (int i = 0; i < 8; ++i) {
            int nn = nnb + (i << 2);
            *(float4*)&Dn[nn * 260 + kq] = pd[i];
            As[nn * 64 + (t & 63)] = __expf(ps[i] - mC) * iC * pcw[i];
        }
        if (nc + 32 < N / NSPLIT) {
            const float* Dg = docs + ((size_t)b * N + n0 + nc + 32) * H;
            const float* Sg = g_scores + ((size_t)b * N + n0 + nc + 32) * C;
            const float* Cg = cw + (size_t)b * N + n0 + nc + 32;
            #pragma unroll
            for (int i = 0; i < 8; ++i) {
                int nn = nnb + (i << 2);
                pd[i] = *(const float4*)(Dg + (size_t)nn * H + kq);
                ps[i] = Sg[(size_t)nn * C + (t & 63)];
                pcw[i] = Cg[nn];
            }
        }
        __syncthreads();

        #pragma unroll 4
        for (int nn = 0; nn < 32; ++nn) {
            float4 d0 = *(const float4*)&Dn[nn * 260 + rowg];
            float4 d1 = *(const float4*)&Dn[nn * 260 + rowg + 4];
            ull u0 = *(const ull*)&As[nn * 64 + colg];
            ull u1 = *(const ull*)&As[nn * 64 + colg + 2];
            ull u2 = *(const ull*)&As[nn * 64 + colg + 4];
            ull u3 = *(const ull*)&As[nn * 64 + colg + 6];
            ull dd;
            dd = pack2(d0.x, d0.x);
            fma2(acc[0][0], dd, u0); fma2(acc[0][1], dd, u1); fma2(acc[0][2], dd, u2); fma2(acc[0][3], dd, u3);
            dd = pack2(d0.y, d0.y);
            fma2(acc[1][0], dd, u0); fma2(acc[1][1], dd, u1); fma2(acc[1][2], dd, u2); fma2(acc[1][3], dd, u3);
            dd = pack2(d0.z, d0.z);
            fma2(acc[2][0], dd, u0); fma2(acc[2][1], dd, u1); fma2(acc[2][2], dd, u2); fma2(acc[2][3], dd, u3);
            dd = pack2(d0.w, d0.w);
            fma2(acc[3][0], dd, u0); fma2(acc[3][1], dd, u1); fma2(acc[3][2], dd, u2); fma2(acc[3][3], dd, u3);
            dd = pack2(d1.x, d1.x);
            fma2(acc[4][0], dd, u0); fma2(acc[4][1], dd, u1); fma2(acc[4][2], dd, u2); fma2(acc[4][3], dd, u3);
            dd = pack2(d1.y, d1.y);
            fma2(acc[5][0], dd, u0); fma2(acc[5][1], dd, u1); fma2(acc[5][2], dd, u2); fma2(acc[5][3], dd, u3);
            dd = pack2(d1.z, d1.z);
            fma2(acc[6][0], dd, u0); fma2(acc[6][1], dd, u1); fma2(acc[6][2], dd, u2); fma2(acc[6][3], dd, u3);
            dd = pack2(d1.w, d1.w);
            fma2(acc[7][0], dd, u0); fma2(acc[7][1], dd, u1); fma2(acc[7][2], dd, u2); fma2(acc[7][3], dd, u3);
        }
    }

    float* Wp = g_Wpart + ((size_t)(b * NSPLIT + ns)) * H * C;
    #pragma unroll
    for (int r = 0; r < 8; ++r) {
        float o[8];
        #pragma unroll
        for (int p = 0; p < 4; ++p) {
            float2 v = unpack2(acc[r][p]);
            o[2 * p] = v.x; o[2 * p + 1] = v.y;
        }
        float* wp = Wp + (size_t)(rowg + r) * C + colg;
        *(float4*)wp       = make_float4(o[0], o[1], o[2], o[3]);
        *(float4*)(wp + 4) = make_float4(o[4], o[5], o[6], o[7]);
    }
}

// ============ K5a: fused k4b-reduce + Wv + Wo + meta, 4 batches per block
__global__ void __launch_bounds__(256) k5a_heads(const float* __restrict__ Wi,
                                                 const float* __restrict__ bi,
                                                 const float* __restrict__ Wo,
                                                 const float* __restrict__ bo,
                                                 const float* __restrict__ M) {
    int f  = blockIdx.x >> 3;   // 0..7
    int bg = blockIdx.x & 7;    // 0..7 -> 4 batches each
    int t = threadIdx.x, lane = t & 31, w = t >> 5;
    __shared__ float ws[32 * 257];    // [(bp*8+h)][k] padded
    __shared__ float ctxs[4][264];
    __shared__ float xs_t[H * 4];     // [k][bp]

    // fused k4b: ws = sum of 4 partials, gathered to [bp][h][k]
    {
        int h = t & 7, bp = (t >> 3) & 3, kb = (t >> 5) * 32;
        int b = bg * 4 + bp;
        const float* base = g_Wpart + ((size_t)b * NSPLIT) * (H * C) + f * NH + h;
        float* wd = &ws[(bp * 8 + h) * 257];
        for (int k = kb; k < kb + 32; ++k) {
            float s = base[(size_t)k * C]
                    + base[(size_t)k * C + H * C]
                    + base[(size_t)k * C + 2 * H * C]
                    + base[(size_t)k * C + 3 * H * C];
            wd[k] = s;
        }
    }
    __syncthreads();

    int bp = w & 3, half = w >> 2;
    const float* Wv = Wi + (size_t)f * 3 * H * H + (size_t)2 * H * H;
    const float* bv = bi + f * 3 * H + 2 * H;
    for (int i0 = half * 128; i0 < half * 128 + 128; i0 += 4) {
        int h = i0 >> 5;
        const float* wsp = &ws[(bp * 8 + h) * 257];
        float s0 = 0.f, s1 = 0.f, s2 = 0.f, s3 = 0.f;
        for (int j = lane; j < H; j += 32) {
            float wv = wsp[j];
            s0 = fmaf(Wv[(size_t)(i0 + 0) * H + j], wv, s0);
            s1 = fmaf(Wv[(size_t)(i0 + 1) * H + j], wv, s1);
            s2 = fmaf(Wv[(size_t)(i0 + 2) * H + j], wv, s2);
            s3 = fmaf(Wv[(size_t)(i0 + 3) * H + j], wv, s3);
        }
        #pragma unroll
        for (int o = 16; o; o >>= 1) {
            s0 += __shfl_xor_sync(0xffffffffu, s0, o);
            s1 += __shfl_xor_sync(0xffffffffu, s1, o);
            s2 += __shfl_xor_sync(0xffffffffu, s2, o);
            s3 += __shfl_xor_sync(0xffffffffu, s3, o);
        }
        if (lane == 0) {
            ctxs[bp][i0 + 0] = s0 + bv[i0 + 0];
            ctxs[bp][i0 + 1] = s1 + bv[i0 + 1];
            ctxs[bp][i0 + 2] = s2 + bv[i0 + 2];
            ctxs[bp][i0 + 3] = s3 + bv[i0 + 3];
        }
    }
    __syncthreads();

    const float* Wof = Wo + (size_t)f * H * H;
    const float* bof = bo + f * H;
    for (int i0 = half * 128; i0 < half * 128 + 128; i0 += 4) {
        float s0 = 0.f, s1 = 0.f, s2 = 0.f, s3 = 0.f;
        for (int j = lane; j < H; j += 32) {
            float cv = ctxs[bp][j];
            s0 = fmaf(Wof[(size_t)(i0 + 0) * H + j], cv, s0);
            s1 = fmaf(Wof[(size_t)(i0 + 1) * H + j], cv, s1);
            s2 = fmaf(Wof[(size_t)(i0 + 2) * H + j], cv, s2);
            s3 = fmaf(Wof[(size_t)(i0 + 3) * H + j], cv, s3);
        }
        #pragma unroll
        for (int o = 16; o; o >>= 1) {
            s0 += __shfl_xor_sync(0xffffffffu, s0, o);
            s1 += __shfl_xor_sync(0xffffffffu, s1, o);
            s2 += __shfl_xor_sync(0xffffffffu, s2, o);
            s3 += __shfl_xor_sync(0xffffffffu, s3, o);
        }
        if (lane == 0) {
            xs_t[(i0 + 0) * 4 + bp] = s0 + bof[i0 + 0];
            xs_t[(i0 + 1) * 4 + bp] = s1 + bof[i0 + 1];
            xs_t[(i0 + 2) * 4 + bp] = s2 + bof[i0 + 2];
            xs_t[(i0 + 3) * 4 + bp] = s3 + bof[i0 + 3];
        }
    }
    __syncthreads();

    // meta steps on xs_t [k][4] with fma2 over batch pairs
    for (int s = 0; s < STEPS; ++s) {
        const float* Ms = M + (size_t)s * H * H;
        ull a0 = *(const ull*)&xs_t[t * 4];
        ull a1 = *(const ull*)&xs_t[t * 4 + 2];
        #pragma unroll 8
        for (int k = 0; k < H; ++k) {
            ull x01 = *(const ull*)&xs_t[k * 4];
            ull x23 = *(const ull*)&xs_t[k * 4 + 2];
            float m = Ms[(size_t)k * H + t];
            ull mm = pack2(m, m);
            fma2(a0, x01, mm);
            fma2(a1, x23, mm);
        }
        __syncthreads();
        *(ull*)&xs_t[t * 4]     = a0;
        *(ull*)&xs_t[t * 4 + 2] = a1;
        __syncthreads();
    }

    float4 v = *(const float4*)&xs_t[t * 4];
    g_ho[((size_t)(f * B + bg * 4 + 0)) * H + t] = v.x;
    g_ho[((size_t)(f * B + bg * 4 + 1)) * H + t] = v.y;
    g_ho[((size_t)(f * B + bg * 4 + 2)) * H + t] = v.z;
    g_ho[((size_t)(f * B + bg * 4 + 3)) * H + t] = v.w;
}

// ============ K5b: strategy softmax + combine
__global__ void __launch_bounds__(256) k5b_out(const float* __restrict__ q,
                                               const float* __restrict__ sw,
                                               const float* __restrict__ sb,
                                               float* __restrict__ out) {
    int b = blockIdx.x;
    int t = threadIdx.x, lane = t & 31, w = t >> 5;
    __shared__ float qs[H];
    __shared__ float lg[F];
    qs[t] = q[b * H + t];
    __syncthreads();
    {
        float s = 0.f;
        for (int j = lane; j < H; j += 32) s = fmaf(sw[(size_t)w * H + j], qs[j], s);
        #pragma unroll
        for (int o = 16; o; o >>= 1) s += __shfl_xor_sync(0xffffffffu, s, o);
        if (lane == 0) lg[w] = s + sb[w];
    }
    __syncthreads();
    float m = lg[0];
    #pragma unroll
    for (int f2 = 1; f2 < F; ++f2) m = fmaxf(m, lg[f2]);
    float p[F], sum = 0.f;
    #pragma unroll
    for (int f2 = 0; f2 < F; ++f2) { p[f2] = __expf(lg[f2] - m); sum += p[f2]; }
    float inv = 1.0f / sum;
    float o = 0.f;
    #pragma unroll
    for (int f2 = 0; f2 < F; ++f2)
        o = fmaf(p[f2] * inv, g_ho[((size_t)(f2 * B + b)) * H + t], o);
    out[b * H + t] = o;
}

extern "C" void kernel_launch(void* const* d_in, const int* in_sizes, int n_in,
                              void* d_out, int out_size) {
    const float* q    = (const float*)d_in[0];
    const float* docs = (const float*)d_in[1];
    const float* cw   = (const float*)d_in[2];
    const float* Wi   = (const float*)d_in[4];
    const float* bi   = (const float*)d_in[5];
    const float* Wo   = (const float*)d_in[6];
    const float* bo   = (const float*)d_in[7];
    const float* sw   = (const float*)d_in[8];
    const float* sb   = (const float*)d_in[9];
    const float* M    = (const float*)d_in[10];
    float* out = (float*)d_out;

    k1_prep<<<B * F, 256>>>(q, Wi, bi);
    k2_scores<<<dim3(NCHUNK, B), 256>>>(docs, cw);
    k4_wgemm<<<dim3(NSPLIT, B), 256>>>(docs, cw);
    k5a_heads<<<F * 8, 256>>>(Wi, bi, Wo, bo, M);
    k5b_out<<<B, 256>>>(q, sw, sb, out);
}

// round 7
// speedup vs baseline: 1.1305x; 1.1305x over previous
#include <cuda_runtime.h>
#include <math.h>

#define B 32
#define N 2048
#define H 256
#define F 8
#define NH 8
#define DH 32
#define C 64
#define STEPS 3
#define NSPLIT 4
#define TN 128
#define NCHUNK 16

typedef unsigned long long ull;

__device__ float  g_U[B * H * C];
__device__ float  g_const[B * C];
__device__ float  g_scores[(size_t)B * N * C];
__device__ float2 g_part[B * NCHUNK * C];
__device__ float  g_Wpart[B * NSPLIT * H * C];
__device__ float  g_ho[F * B * H];
__device__ float  g_ho2[F * B * H];

__device__ __forceinline__ ull pack2(float x, float y) {
    ull r; asm("mov.b64 %0, {%1, %2};" : "=l"(r) : "f"(x), "f"(y)); return r;
}
__device__ __forceinline__ float2 unpack2(ull v) {
    float2 r; asm("mov.b64 {%0, %1}, %2;" : "=f"(r.x), "=f"(r.y) : "l"(v)); return r;
}
__device__ __forceinline__ void fma2(ull& a, ull x, ull y) {
    asm("fma.rn.f32x2 %0, %1, %2, %0;" : "+l"(a) : "l"(x), "l"(y));
}

// ============ K1: qh = Wq q + bq ; U = Wk^T qh / sqrt(dh) ; const = qh.bk/sqrt(dh)
__global__ void __launch_bounds__(256) k1_prep(const float* __restrict__ q,
                                               const float* __restrict__ Wi,
                                               const float* __restrict__ bi) {
    int f = blockIdx.x & (F - 1);
    int b = blockIdx.x >> 3;
    __shared__ float qs[H];
    __shared__ float qhs[H];
    int t = threadIdx.x, lane = t & 31, w = t >> 5;
    qs[t] = q[b * H + t];
    __syncthreads();

    const float* Wq = Wi + (size_t)f * 3 * H * H;
    const float* bq = bi + f * 3 * H;
    for (int i0 = w * 32; i0 < w * 32 + 32; i0 += 4) {
        float s0 = 0.f, s1 = 0.f, s2 = 0.f, s3 = 0.f;
        for (int j = lane; j < H; j += 32) {
            float qv = qs[j];
            s0 = fmaf(Wq[(size_t)(i0 + 0) * H + j], qv, s0);
            s1 = fmaf(Wq[(size_t)(i0 + 1) * H + j], qv, s1);
            s2 = fmaf(Wq[(size_t)(i0 + 2) * H + j], qv, s2);
            s3 = fmaf(Wq[(size_t)(i0 + 3) * H + j], qv, s3);
        }
        #pragma unroll
        for (int o = 16; o; o >>= 1) {
            s0 += __shfl_xor_sync(0xffffffffu, s0, o);
            s1 += __shfl_xor_sync(0xffffffffu, s1, o);
            s2 += __shfl_xor_sync(0xffffffffu, s2, o);
            s3 += __shfl_xor_sync(0xffffffffu, s3, o);
        }
        if (lane == 0) {
            qhs[i0 + 0] = s0 + bq[i0 + 0];
            qhs[i0 + 1] = s1 + bq[i0 + 1];
            qhs[i0 + 2] = s2 + bq[i0 + 2];
            qhs[i0 + 3] = s3 + bq[i0 + 3];
        }
    }
    __syncthreads();

    const float invs = 0.17677669529663687f;
    const float* Wk = Wi + (size_t)f * 3 * H * H + (size_t)H * H;
    float uo[NH];
    #pragma unroll
    for (int h = 0; h < NH; ++h) {
        float s = 0.f;
        #pragma unroll 8
        for (int j = 0; j < DH; ++j)
            s = fmaf(qhs[h * DH + j], Wk[(size_t)(h * DH + j) * H + t], s);
        uo[h] = s * invs;
    }
    float* up = g_U + ((size_t)(b * H + t)) * C + f * NH;
    *(float4*)up       = make_float4(uo[0], uo[1], uo[2], uo[3]);
    *(float4*)(up + 4) = make_float4(uo[4], uo[5], uo[6], uo[7]);

    if (t < NH) {
        const float* bk = bi + f * 3 * H + H;
        float s = 0.f;
        for (int j = 0; j < DH; ++j) s += qhs[t * DH + j] * bk[t * DH + j];
        g_const[b * C + f * NH + t] = s * invs;
    }
}

// ============ K2: scores GEMM (double-buffered) + fused partial softmax stats
__global__ void __launch_bounds__(256) k2_scores(const float* __restrict__ docs,
                                                 const float* __restrict__ cw) {
    int b = blockIdx.y;
    int chunk = blockIdx.x;
    int n0 = chunk * TN;
    __shared__ __align__(16) float Ds[32 * 132];
    __shared__ __align__(16) float Us[32 * 64];
    int t = threadIdx.x;
    int rowg = (t >> 3) << 2;
    int colg = (t & 7) << 3;
    ull acc[4][4];
    #pragma unroll
    for (int r = 0; r < 4; ++r)
        #pragma unroll
        for (int p = 0; p < 4; ++p) acc[r][p] = 0ull;

    const float* Db = docs + ((size_t)b * N + n0) * H;
    const float* Ub = g_U + (size_t)b * H * C;
    int lk = (t & 7) << 2;
    int lr = t >> 3;
    int uk = t >> 3;
    int uc = (t & 7) << 3;

    float4 pd[4], pu0, pu1;
    #pragma unroll
    for (int it = 0; it < 4; ++it)
        pd[it] = *(const float4*)(Db + (size_t)(lr + (it << 5)) * H + lk);
    pu0 = *(const float4*)(Ub + (size_t)uk * C + uc);
    pu1 = *(const float4*)(Ub + (size_t)uk * C + uc + 4);

    for (int k0 = 0; k0 < H; k0 += 32) {
        if (k0) __syncthreads();
        #pragma unroll
        for (int it = 0; it < 4; ++it) {
            int r = lr + (it << 5);
            Ds[(lk + 0) * 132 + r] = pd[it].x;
            Ds[(lk + 1) * 132 + r] = pd[it].y;
            Ds[(lk + 2) * 132 + r] = pd[it].z;
            Ds[(lk + 3) * 132 + r] = pd[it].w;
        }
        *(float4*)&Us[uk * 64 + uc]     = pu0;
        *(float4*)&Us[uk * 64 + uc + 4] = pu1;
        if (k0 + 32 < H) {
            #pragma unroll
            for (int it = 0; it < 4; ++it)
                pd[it] = *(const float4*)(Db + (size_t)(lr + (it << 5)) * H + (k0 + 32 + lk));
            pu0 = *(const float4*)(Ub + (size_t)(k0 + 32 + uk) * C + uc);
            pu1 = *(const float4*)(Ub + (size_t)(k0 + 32 + uk) * C + uc + 4);
        }
        __syncthreads();

        #pragma unroll 8
        for (int k = 0; k < 32; ++k) {
            float4 d4 = *(const float4*)&Ds[k * 132 + rowg];
            ull u0 = *(const ull*)&Us[k * 64 + colg];
            ull u1 = *(const ull*)&Us[k * 64 + colg + 2];
            ull u2 = *(const ull*)&Us[k * 64 + colg + 4];
            ull u3 = *(const ull*)&Us[k * 64 + colg + 6];
            ull dd;
            dd = pack2(d4.x, d4.x);
            fma2(acc[0][0], dd, u0); fma2(acc[0][1], dd, u1); fma2(acc[0][2], dd, u2); fma2(acc[0][3], dd, u3);
            dd = pack2(d4.y, d4.y);
            fma2(acc[1][0], dd, u0); fma2(acc[1][1], dd, u1); fma2(acc[1][2], dd, u2); fma2(acc[1][3], dd, u3);
            dd = pack2(d4.z, d4.z);
            fma2(acc[2][0], dd, u0); fma2(acc[2][1], dd, u1); fma2(acc[2][2], dd, u2); fma2(acc[2][3], dd, u3);
            dd = pack2(d4.w, d4.w);
            fma2(acc[3][0], dd, u0); fma2(acc[3][1], dd, u1); fma2(acc[3][2], dd, u2); fma2(acc[3][3], dd, u3);
        }
    }

    float cst[8];
    #pragma unroll
    for (int c = 0; c < 8; ++c) cst[c] = g_const[b * C + colg + c];
    const float* cwp = cw + (size_t)b * N + n0;
    float o[4][8];
    #pragma unroll
    for (int r = 0; r < 4; ++r) {
        float cwv = cwp[rowg + r];
        #pragma unroll
        for (int p = 0; p < 4; ++p) {
            float2 v = unpack2(acc[r][p]);
            o[r][2 * p]     = fmaf(cwv, v.x, cst[2 * p]);
            o[r][2 * p + 1] = fmaf(cwv, v.y, cst[2 * p + 1]);
        }
        float* sp = g_scores + ((size_t)b * N + n0 + rowg + r) * C + colg;
        *(float4*)sp       = make_float4(o[r][0], o[r][1], o[r][2], o[r][3]);
        *(float4*)(sp + 4) = make_float4(o[r][4], o[r][5], o[r][6], o[r][7]);
    }

    __syncthreads();
    float* red  = Ds;
    float* smax = Us;
    int j = t >> 3;
    #pragma unroll
    for (int c = 0; c < 8; ++c) {
        float lm = fmaxf(fmaxf(o[0][c], o[1][c]), fmaxf(o[2][c], o[3][c]));
        red[j * 65 + colg + c] = lm;
    }
    __syncthreads();
    if (t < 64) {
        float m = -1e30f;
        #pragma unroll
        for (int jj = 0; jj < 32; ++jj) m = fmaxf(m, red[jj * 65 + t]);
        smax[t] = m;
    }
    __syncthreads();
    #pragma unroll
    for (int c = 0; c < 8; ++c) {
        float m = smax[colg + c];
        float ls = __expf(o[0][c] - m) + __expf(o[1][c] - m) +
                   __expf(o[2][c] - m) + __expf(o[3][c] - m);
        red[j * 65 + colg + c] = ls;
    }
    __syncthreads();
    if (t < 64) {
        float l = 0.f;
        #pragma unroll
        for (int jj = 0; jj < 32; ++jj) l += red[jj * 65 + t];
        g_part[(b * NCHUNK + chunk) * C + t] = make_float2(smax[t], l);
    }
}

// ============ K4: fused stat-merge + Wpart GEMM (double-buffered)
__global__ void __launch_bounds__(256) k4_wgemm(const float* __restrict__ docs,
                                                const float* __restrict__ cw) {
    int b = blockIdx.y, ns = blockIdx.x;
    int n0 = ns * (N / NSPLIT);
    __shared__ __align__(16) float Dn[32 * 260];
    __shared__ __align__(16) float As[32 * 64];
    __shared__ float msh[64], ilh[64];
    int t = threadIdx.x;

    if (t < 64) {
        float2 pc[NCHUNK];
        float m = -1e30f;
        #pragma unroll
        for (int ch = 0; ch < NCHUNK; ++ch) {
            pc[ch] = g_part[(b * NCHUNK + ch) * C + t];
            m = fmaxf(m, pc[ch].x);
        }
        float l = 0.f;
        #pragma unroll
        for (int ch = 0; ch < NCHUNK; ++ch) l += pc[ch].y * __expf(pc[ch].x - m);
        msh[t] = m; ilh[t] = 1.0f / l;
    }
    __syncthreads();
    float mC = msh[t & 63], iC = ilh[t & 63];

    int rowg = (t >> 3) << 3;
    int colg = (t & 7) << 3;
    ull acc[8][4];
    #pragma unroll
    for (int r = 0; r < 8; ++r)
        #pragma unroll
        for (int p = 0; p < 4; ++p) acc[r][p] = 0ull;

    float4 pd[8];
    float  ps[8], pcw[8];
    int kq = (t & 63) << 2;
    int nnb = t >> 6;

    {
        const float* Dg = docs + ((size_t)b * N + n0) * H;
        const float* Sg = g_scores + ((size_t)b * N + n0) * C;
        const float* Cg = cw + (size_t)b * N + n0;
        #pragma unroll
        for (int i = 0; i < 8; ++i) {
            int nn = nnb + (i << 2);
            pd[i] = *(const float4*)(Dg + (size_t)nn * H + kq);
            ps[i] = Sg[(size_t)nn * C + (t & 63)];
            pcw[i] = Cg[nn];
        }
    }

    for (int nc = 0; nc < N / NSPLIT; nc += 32) {
        if (nc) __syncthreads();
        #pragma unroll
        for (int i = 0; i < 8; ++i) {
            int nn = nnb + (i << 2);
            *(float4*)&Dn[nn * 260 + kq] = pd[i];
            As[nn * 64 + (t & 63)] = __expf(ps[i] - mC) * iC * pcw[i];
        }
        if (nc + 32 < N / NSPLIT) {
            const float* Dg = docs + ((size_t)b * N + n0 + nc + 32) * H;
            const float* Sg = g_scores + ((size_t)b * N + n0 + nc + 32) * C;
            const float* Cg = cw + (size_t)b * N + n0 + nc + 32;
            #pragma unroll
            for (int i = 0; i < 8; ++i) {
                int nn = nnb + (i << 2);
                pd[i] = *(const float4*)(Dg + (size_t)nn * H + kq);
                ps[i] = Sg[(size_t)nn * C + (t & 63)];
                pcw[i] = Cg[nn];
            }
        }
        __syncthreads();

        #pragma unroll 4
        for (int nn = 0; nn < 32; ++nn) {
            float4 d0 = *(const float4*)&Dn[nn * 260 + rowg];
            float4 d1 = *(const float4*)&Dn[nn * 260 + rowg + 4];
            ull u0 = *(const ull*)&As[nn * 64 + colg];
            ull u1 = *(const ull*)&As[nn * 64 + colg + 2];
            ull u2 = *(const ull*)&As[nn * 64 + colg + 4];
            ull u3 = *(const ull*)&As[nn * 64 + colg + 6];
            ull dd;
            dd = pack2(d0.x, d0.x);
            fma2(acc[0][0], dd, u0); fma2(acc[0][1], dd, u1); fma2(acc[0][2], dd, u2); fma2(acc[0][3], dd, u3);
            dd = pack2(d0.y, d0.y);
            fma2(acc[1][0], dd, u0); fma2(acc[1][1], dd, u1); fma2(acc[1][2], dd, u2); fma2(acc[1][3], dd, u3);
            dd = pack2(d0.z, d0.z);
            fma2(acc[2][0], dd, u0); fma2(acc[2][1], dd, u1); fma2(acc[2][2], dd, u2); fma2(acc[2][3], dd, u3);
            dd = pack2(d0.w, d0.w);
            fma2(acc[3][0], dd, u0); fma2(acc[3][1], dd, u1); fma2(acc[3][2], dd, u2); fma2(acc[3][3], dd, u3);
            dd = pack2(d1.x, d1.x);
            fma2(acc[4][0], dd, u0); fma2(acc[4][1], dd, u1); fma2(acc[4][2], dd, u2); fma2(acc[4][3], dd, u3);
            dd = pack2(d1.y, d1.y);
            fma2(acc[5][0], dd, u0); fma2(acc[5][1], dd, u1); fma2(acc[5][2], dd, u2); fma2(acc[5][3], dd, u3);
            dd = pack2(d1.z, d1.z);
            fma2(acc[6][0], dd, u0); fma2(acc[6][1], dd, u1); fma2(acc[6][2], dd, u2); fma2(acc[6][3], dd, u3);
            dd = pack2(d1.w, d1.w);
            fma2(acc[7][0], dd, u0); fma2(acc[7][1], dd, u1); fma2(acc[7][2], dd, u2); fma2(acc[7][3], dd, u3);
        }
    }

    float* Wp = g_Wpart + ((size_t)(b * NSPLIT + ns)) * H * C;
    #pragma unroll
    for (int r = 0; r < 8; ++r) {
        float o[8];
        #pragma unroll
        for (int p = 0; p < 4; ++p) {
            float2 v = unpack2(acc[r][p]);
            o[2 * p] = v.x; o[2 * p + 1] = v.y;
        }
        float* wp = Wp + (size_t)(rowg + r) * C + colg;
        *(float4*)wp       = make_float4(o[0], o[1], o[2], o[3]);
        *(float4*)(wp + 4) = make_float4(o[4], o[5], o[6], o[7]);
    }
}

// ============ kA: per-(f,b) fused reduce + Wv + Wo  (256 blocks)
__global__ void __launch_bounds__(256) kA_ctx(const float* __restrict__ Wi,
                                              const float* __restrict__ bi,
                                              const float* __restrict__ Wo,
                                              const float* __restrict__ bo) {
    int f = blockIdx.x >> 5;
    int b = blockIdx.x & 31;
    int t = threadIdx.x, lane = t & 31, w = t >> 5;
    __shared__ float ws[8][264];
    __shared__ float ctxs[264];
    __shared__ float xs[H];

    {
        int h = t & 7, k0 = t >> 3;
        const float* base = g_Wpart + (size_t)(b * NSPLIT) * (H * C) + f * NH + h;
        #pragma unroll
        for (int i = 0; i < 8; ++i) {
            int k = k0 + 32 * i;
            float s = base[(size_t)k * C]
                    + base[(size_t)k * C + H * C]
                    + base[(size_t)k * C + 2 * H * C]
                    + base[(size_t)k * C + 3 * H * C];
            ws[h][k] = s;
        }
    }
    __syncthreads();

    const float* Wv = Wi + (size_t)f * 3 * H * H + (size_t)2 * H * H;
    const float* bv = bi + f * 3 * H + 2 * H;
    for (int i0 = w * 32; i0 < w * 32 + 32; i0 += 4) {
        const float* wsp = ws[i0 >> 5];
        float s0 = 0.f, s1 = 0.f, s2 = 0.f, s3 = 0.f;
        for (int j = lane; j < H; j += 32) {
            float wv = wsp[j];
            s0 = fmaf(Wv[(size_t)(i0 + 0) * H + j], wv, s0);
            s1 = fmaf(Wv[(size_t)(i0 + 1) * H + j], wv, s1);
            s2 = fmaf(Wv[(size_t)(i0 + 2) * H + j], wv, s2);
            s3 = fmaf(Wv[(size_t)(i0 + 3) * H + j], wv, s3);
        }
        #pragma unroll
        for (int o = 16; o; o >>= 1) {
            s0 += __shfl_xor_sync(0xffffffffu, s0, o);
            s1 += __shfl_xor_sync(0xffffffffu, s1, o);
            s2 += __shfl_xor_sync(0xffffffffu, s2, o);
            s3 += __shfl_xor_sync(0xffffffffu, s3, o);
        }
        if (lane == 0) {
            ctxs[i0 + 0] = s0 + bv[i0 + 0];
            ctxs[i0 + 1] = s1 + bv[i0 + 1];
            ctxs[i0 + 2] = s2 + bv[i0 + 2];
            ctxs[i0 + 3] = s3 + bv[i0 + 3];
        }
    }
    __syncthreads();

    const float* Wof = Wo + (size_t)f * H * H;
    const float* bof = bo + f * H;
    for (int i0 = w * 32; i0 < w * 32 + 32; i0 += 4) {
        float s0 = 0.f, s1 = 0.f, s2 = 0.f, s3 = 0.f;
        for (int j = lane; j < H; j += 32) {
            float cv = ctxs[j];
            s0 = fmaf(Wof[(size_t)(i0 + 0) * H + j], cv, s0);
            s1 = fmaf(Wof[(size_t)(i0 + 1) * H + j], cv, s1);
            s2 = fmaf(Wof[(size_t)(i0 + 2) * H + j], cv, s2);
            s3 = fmaf(Wof[(size_t)(i0 + 3) * H + j], cv, s3);
        }
        #pragma unroll
        for (int o = 16; o; o >>= 1) {
            s0 += __shfl_xor_sync(0xffffffffu, s0, o);
            s1 += __shfl_xor_sync(0xffffffffu, s1, o);
            s2 += __shfl_xor_sync(0xffffffffu, s2, o);
            s3 += __shfl_xor_sync(0xffffffffu, s3, o);
        }
        if (lane == 0) {
            xs[i0 + 0] = s0 + bof[i0 + 0];
            xs[i0 + 1] = s1 + bof[i0 + 1];
            xs[i0 + 2] = s2 + bof[i0 + 2];
            xs[i0 + 3] = s3 + bof[i0 + 3];
        }
    }
    __syncthreads();
    g_ho[((size_t)(f * B + b)) * H + t] = xs[t];
}

// ============ k_meta: Y = X + X @ M  (X: [F*B=256, H], tiled GEMM)
__global__ void __launch_bounds__(256) k_meta(const float* __restrict__ X,
                                              const float* __restrict__ M,
                                              float* __restrict__ Y) {
    int c0 = blockIdx.x * 64;
    int r0 = blockIdx.y * 32;
    __shared__ __align__(16) float Xs[32 * 36];
    __shared__ __align__(16) float Ms[32 * 68];
    int t = threadIdx.x;
    int r = t >> 3, cg = (t & 7) << 3;
    ull acc[4] = {0ull, 0ull, 0ull, 0ull};

    for (int kc = 0; kc < H; kc += 32) {
        {
            int rr = t >> 3, kk = (t & 7) << 2;
            *(float4*)&Xs[rr * 36 + kk] = *(const float4*)(X + (size_t)(r0 + rr) * H + kc + kk);
        }
        {
            int kk = t >> 3, cc = (t & 7) << 3;
            *(float4*)&Ms[kk * 68 + cc]     = *(const float4*)(M + (size_t)(kc + kk) * H + c0 + cc);
            *(float4*)&Ms[kk * 68 + cc + 4] = *(const float4*)(M + (size_t)(kc + kk) * H + c0 + cc + 4);
        }
        __syncthreads();
        #pragma unroll
        for (int k = 0; k < 32; ++k) {
            float x = Xs[r * 36 + k];
            ull xx = pack2(x, x);
            fma2(acc[0], xx, *(const ull*)&Ms[k * 68 + cg]);
            fma2(acc[1], xx, *(const ull*)&Ms[k * 68 + cg + 2]);
            fma2(acc[2], xx, *(const ull*)&Ms[k * 68 + cg + 4]);
            fma2(acc[3], xx, *(const ull*)&Ms[k * 68 + cg + 6]);
        }
        __syncthreads();
    }

    const float* xr = X + (size_t)(r0 + r) * H + c0 + cg;
    float4 a0 = *(const float4*)xr;
    float4 a1 = *(const float4*)(xr + 4);
    float2 v0 = unpack2(acc[0]), v1 = unpack2(acc[1]), v2 = unpack2(acc[2]), v3 = unpack2(acc[3]);
    float* yr = Y + (size_t)(r0 + r) * H + c0 + cg;
    *(float4*)yr       = make_float4(a0.x + v0.x, a0.y + v0.y, a0.z + v1.x, a0.w + v1.y);
    *(float4*)(yr + 4) = make_float4(a1.x + v2.x, a1.y + v2.y, a1.z + v3.x, a1.w + v3.y);
}

// ============ K5b: strategy softmax + combine (reads g_ho2 after 3 meta steps)
__global__ void __launch_bounds__(256) k5b_out(const float* __restrict__ q,
                                               const float* __restrict__ sw,
                                               const float* __restrict__ sb,
                                               float* __restrict__ out) {
    int b = blockIdx.x;
    int t = threadIdx.x, lane = t & 31, w = t >> 5;
    __shared__ float qs[H];
    __shared__ float lg[F];
    qs[t] = q[b * H + t];
    __syncthreads();
    {
        float s = 0.f;
        for (int j = lane; j < H; j += 32) s = fmaf(sw[(size_t)w * H + j], qs[j], s);
        #pragma unroll
        for (int o = 16; o; o >>= 1) s += __shfl_xor_sync(0xffffffffu, s, o);
        if (lane == 0) lg[w] = s + sb[w];
    }
    __syncthreads();
    float m = lg[0];
    #pragma unroll
    for (int f2 = 1; f2 < F; ++f2) m = fmaxf(m, lg[f2]);
    float p[F], sum = 0.f;
    #pragma unroll
    for (int f2 = 0; f2 < F; ++f2) { p[f2] = __expf(lg[f2] - m); sum += p[f2]; }
    float inv = 1.0f / sum;
    float o = 0.f;
    #pragma unroll
    for (int f2 = 0; f2 < F; ++f2)
        o = fmaf(p[f2] * inv, g_ho2[((size_t)(f2 * B + b)) * H + t], o);
    out[b * H + t] = o;
}

extern "C" void kernel_launch(void* const* d_in, const int* in_sizes, int n_in,
                              void* d_out, int out_size) {
    const float* q    = (const float*)d_in[0];
    const float* docs = (const float*)d_in[1];
    const float* cw   = (const float*)d_in[2];
    const float* Wi   = (const float*)d_in[4];
    const float* bi   = (const float*)d_in[5];
    const float* Wo   = (const float*)d_in[6];
    const float* bo   = (const float*)d_in[7];
    const float* sw   = (const float*)d_in[8];
    const float* sb   = (const float*)d_in[9];
    const float* M    = (const float*)d_in[10];
    float* out = (float*)d_out;

    float* ho;  cudaGetSymbolAddress((void**)&ho,  g_ho);
    float* ho2; cudaGetSymbolAddress((void**)&ho2, g_ho2);

    k1_prep<<<B * F, 256>>>(q, Wi, bi);
    k2_scores<<<dim3(NCHUNK, B), 256>>>(docs, cw);
    k4_wgemm<<<dim3(NSPLIT, B), 256>>>(docs, cw);
    kA_ctx<<<F * B, 256>>>(Wi, bi, Wo, bo);
    k_meta<<<dim3(4, 8), 256>>>(ho,  M,                 ho2);
    k_meta<<<dim3(4, 8), 256>>>(ho2, M + (size_t)H * H, ho);
    k_meta<<<dim3(4, 8), 256>>>(ho,  M + (size_t)2 * H * H, ho2);
    k5b_out<<<B, 256>>>(q, sw, sb, out);
}